// round 17
// baseline (speedup 1.0000x reference)
#include <cuda_runtime.h>

typedef unsigned long long u64;

__device__ __forceinline__ u64 pk2(float lo, float hi) {
    u64 r; asm("mov.b64 %0,{%1,%2};" : "=l"(r) : "f"(lo), "f"(hi)); return r;
}
__device__ __forceinline__ u64 fma2(u64 a, u64 b, u64 c) {
    u64 d; asm("fma.rn.f32x2 %0,%1,%2,%3;" : "=l"(d) : "l"(a), "l"(b), "l"(c)); return d;
}
__device__ __forceinline__ float sum2(u64 a) {
    float lo, hi; asm("mov.b64 {%0,%1},%2;" : "=f"(lo), "=f"(hi) : "l"(a)); return lo + hi;
}
__device__ __forceinline__ unsigned smem_u32(const void* p) {
    unsigned a;
    asm("{ .reg .u64 t; cvta.to.shared.u64 t, %1; cvt.u32.u64 %0, t; }" : "=r"(a) : "l"(p));
    return a;
}
__device__ __forceinline__ void cp_async16(unsigned s, const void* g) {
    asm volatile("cp.async.cg.shared.global [%0], [%1], 16;" :: "r"(s), "l"(g));
}

// Scratch — written by the PDL-primary k_gcn, read by k_adj with PLAIN loads
// only (never __ldg/ld.global.nc: nc is licensed to bypass the PDL ordering).
__device__ float g_n1[2048 * 8];     // n1[row][k]
__device__ float g_n2T[6 * 2048];    // n2 transposed [k][row]

// ---------------------------------------------------------------------------
// k_gcn — r6-proven body (~21us): 256 blocks x 512 threads.
// ---------------------------------------------------------------------------
__global__ void __launch_bounds__(512) k_gcn(const float* __restrict__ x,
                                             const float* __restrict__ wa,
                                             const float* __restrict__ Ww,
                                             const float* __restrict__ Wb,
                                             const float* __restrict__ Wx_w,
                                             const float* __restrict__ Wxx,
                                             const float* __restrict__ Wxxb,
                                             float* __restrict__ out) {
    cudaTriggerProgrammaticLaunchCompletion();

    __shared__ __align__(16) float pool[8192];
    __shared__ __align__(16) float a_s[4][128];
    __shared__ __align__(16) float t_s[1024];
    __shared__ __align__(16) float g_s[1024];

    int b    = blockIdx.x >> 5;
    int i0   = (blockIdx.x & 31) << 3;
    int tid  = threadIdx.x;
    int g    = tid >> 7;
    int lane = tid & 127;
    int rh   = g & 1;
    int jh   = g >> 1;
    int jtid = tid & 255;
    int r0   = blockIdx.x * 8;
    const float inv6 = 1.0f / 6.0f;

    // ---- Phase A: t = mean_h(wa) @ x ----
    float* x_s = pool + jh * 4096;
    u64 acc[4];
    #pragma unroll
    for (int ii = 0; ii < 4; ii++) acc[ii] = 0ull;

    for (int jt = 0; jt < 4; jt++) {
        int j0 = jh * 128 + jt * 32;
        const float4* xs = (const float4*)(x + ((long)b * 256 + j0) * 128);
        float4*       xd = (float4*)x_s;
        #pragma unroll
        for (int idx = jtid; idx < 1024; idx += 256) xd[idx] = xs[idx];
        {
            int ii = lane >> 5, jj = lane & 31;
            float s = 0.0f;
            #pragma unroll
            for (int h = 0; h < 6; h++)
                s += wa[(((long)(b * 6 + h) * 256) + i0 + rh * 4 + ii) * 256 + j0 + jj];
            a_s[g][lane] = s * inv6;
        }
        __syncthreads();
        #pragma unroll
        for (int gg = 0; gg < 32; gg += 4) {
            float xv0 = x_s[(gg + 0) * 128 + lane];
            float xv1 = x_s[(gg + 1) * 128 + lane];
            float xv2 = x_s[(gg + 2) * 128 + lane];
            float xv3 = x_s[(gg + 3) * 128 + lane];
            u64 xp0 = pk2(xv0, xv1), xp1 = pk2(xv2, xv3);
            #pragma unroll
            for (int ii = 0; ii < 4; ii++) {
                const u64* ap = (const u64*)&a_s[g][ii * 32 + gg];
                acc[ii] = fma2(ap[0], xp0, acc[ii]);
                acc[ii] = fma2(ap[1], xp1, acc[ii]);
            }
        }
        __syncthreads();
    }
    #pragma unroll
    for (int ii = 0; ii < 4; ii++) pool[g * 512 + ii * 128 + lane] = sum2(acc[ii]);
    __syncthreads();
    #pragma unroll
    for (int idx = tid; idx < 1024; idx += 512) {
        int r = idx >> 7, c = idx & 127;
        int rhh = r >> 2, rr = r & 3;
        t_s[idx] = pool[rhh * 512 + rr * 128 + c] + pool[(2 + rhh) * 512 + rr * 128 + c];
    }
    __syncthreads();

    // ---- Phase B: gcn = relu(t @ Ww^T + b) ----
    float* w_s = pool;
    u64 b2[2];
    b2[0] = b2[1] = 0ull;
    for (int kt = 0; kt < 4; kt++) {
        int k0 = kt * 32;
        #pragma unroll
        for (int idx = tid; idx < 4096; idx += 512) {
            int d = idx >> 5, c = idx & 31;
            w_s[c * 129 + d] = Ww[d * 128 + k0 + c];
        }
        __syncthreads();
        #pragma unroll
        for (int kk = 0; kk < 32; kk += 2) {
            u64 wp = pk2(w_s[kk * 129 + lane], w_s[(kk + 1) * 129 + lane]);
            #pragma unroll
            for (int r = 0; r < 2; r++) {
                u64 t2 = *(const u64*)&t_s[(g * 2 + r) * 128 + k0 + kk];
                b2[r] = fma2(t2, wp, b2[r]);
            }
        }
        __syncthreads();
    }
    float bb = Wb[lane];
    #pragma unroll
    for (int r = 0; r < 2; r++)
        g_s[(g * 2 + r) * 128 + lane] = fmaxf(sum2(b2[r]) + bb, 0.0f);
    __syncthreads();

    // ---- Phase C: out = gcn @ Wxx^T + b ----
    u64 o2[2];
    o2[0] = o2[1] = 0ull;
    for (int kt = 0; kt < 4; kt++) {
        int k0 = kt * 32;
        #pragma unroll
        for (int idx = tid; idx < 4096; idx += 512) {
            int d = idx >> 5, c = idx & 31;
            w_s[c * 129 + d] = Wxx[d * 128 + k0 + c];
        }
        __syncthreads();
        #pragma unroll
        for (int kk = 0; kk < 32; kk += 2) {
            u64 wp = pk2(w_s[kk * 129 + lane], w_s[(kk + 1) * 129 + lane]);
            #pragma unroll
            for (int r = 0; r < 2; r++) {
                u64 g2 = *(const u64*)&g_s[(g * 2 + r) * 128 + k0 + kk];
                o2[r] = fma2(g2, wp, o2[r]);
            }
        }
        __syncthreads();
    }
    float ob = Wxxb[lane];
    #pragma unroll
    for (int r = 0; r < 2; r++)
        out[(long)(r0 + g * 2 + r) * 128 + lane] = sum2(o2[r]) + ob;

    // ---- Phase D: n1/n2 ----
    if (tid < 96) {
        int sel = tid >= 48;
        int q   = tid - sel * 48;
        int r   = q / 6, k = q % 6;
        const float* gp = g_s + r * 128;
        const float* w  = Wx_w + k * 294 + 6 + sel * 128;
        u64 s = 0ull;
        #pragma unroll 8
        for (int d = 0; d < 128; d += 2)
            s = fma2(*(const u64*)&gp[d], pk2(__ldg(&w[d]), __ldg(&w[d + 1])), s);
        float v = sum2(s);
        if (sel == 0) g_n1[(r0 + r) * 8 + k]   = v;
        else          g_n2T[k * 2048 + r0 + r] = v;
    }
}

// ---------------------------------------------------------------------------
// k_adj — warp-independent pipelines (r16 structure), n1/n2 via PLAIN loads.
// ---------------------------------------------------------------------------
__global__ void __launch_bounds__(256, 6) k_adj(const float* __restrict__ wa,
                                                const float* __restrict__ e,
                                                const float* __restrict__ Wx_w,
                                                const float* __restrict__ Wx_b,
                                                float* __restrict__ adj_out) {
    __shared__ __align__(16) float e_s[256 * 36];  // [j][36]: cf on both sides
    __shared__ __align__(16) float Wa_s[40];       // [k*6+h]
    __shared__ __align__(16) float We_s[200];      // [k*32+ee]
    int b    = blockIdx.x >> 8;
    int i    = blockIdx.x & 255;
    int tid  = threadIdx.x;
    int wrp  = tid >> 5;
    int ln   = tid & 31;

    // (a) per-warp e staging: warp w owns j in [32w, 32w+32)
    const float4* e4 = (const float4*)(e + (((long)b * 256 + i) * 256) * 32) + (wrp << 8);
    #pragma unroll
    for (int q = 0; q < 8; q++) {
        int idx = q * 32 + ln;
        int j   = (wrp << 5) + (idx >> 3);
        int c   = idx & 7;
        cp_async16(smem_u32(&e_s[j * 36 + c * 4]), &e4[idx]);
    }
    asm volatile("cp.async.commit_group;" ::: "memory");

    // (b) per-thread + tiny shared staging (overlaps the async copies)
    float wv[6];
    #pragma unroll
    for (int h = 0; h < 6; h++)
        wv[h] = wa[(((long)(b * 6 + h) * 256) + i) * 256 + tid];
    if (tid < 36) Wa_s[tid] = Wx_w[(tid / 6) * 294 + tid % 6];
    if (tid >= 64 && tid < 256) {
        int t = tid - 64;
        We_s[t] = Wx_w[(t >> 5) * 294 + 262 + (t & 31)];
    }

    // (c) barrier only for Wa_s/We_s — before the e-wait
    __syncthreads();

    // (d) per-warp wait on own async group
    asm volatile("cp.async.wait_group 0;" ::: "memory");
    __syncwarp();

    // (e) heavy compute — warps proceed independently
    u64 acc2[6];
    #pragma unroll
    for (int k = 0; k < 6; k++) acc2[k] = 0ull;

    u64 wp0 = pk2(wv[0], wv[1]), wp1 = pk2(wv[2], wv[3]), wp2 = pk2(wv[4], wv[5]);
    #pragma unroll
    for (int k = 0; k < 6; k++) {
        acc2[k] = fma2(*(const u64*)&Wa_s[k * 6 + 0], wp0, acc2[k]);
        acc2[k] = fma2(*(const u64*)&Wa_s[k * 6 + 2], wp1, acc2[k]);
        acc2[k] = fma2(*(const u64*)&Wa_s[k * 6 + 4], wp2, acc2[k]);
    }

    const float4* ep = (const float4*)&e_s[tid * 36];
    #pragma unroll
    for (int q = 0; q < 8; q++) {
        float4 w = ep[q];
        u64 ev0 = pk2(w.x, w.y);
        u64 ev1 = pk2(w.z, w.w);
        #pragma unroll
        for (int k = 0; k < 6; k++) {
            acc2[k] = fma2(ev0, *(const u64*)&We_s[k * 32 + q * 4 + 0], acc2[k]);
            acc2[k] = fma2(ev1, *(const u64*)&We_s[k * 32 + q * 4 + 2], acc2[k]);
        }
    }

    // (f) wait for the PDL primary's n1/n2 writes
    cudaGridDependencySynchronize();

    // (g) fold + store. PLAIN loads for g_n1/g_n2T (PDL-ordered);
    //     __ldg only for the true-constant Wx_b.
    const float* n1p = &g_n1[((long)b * 256 + i) * 8];
    long ob = ((long)(b * 6) * 65536) + (long)i * 256 + tid;
    #pragma unroll
    for (int k = 0; k < 6; k++) {
        float n1v = n1p[k];                             // plain, block-uniform
        float bsv = __ldg(&Wx_b[k]);                    // input constant
        float n2v = g_n2T[k * 2048 + b * 256 + tid];    // plain, coalesced
        adj_out[ob + (long)k * 65536] = sum2(acc2[k]) + n1v + bsv + n2v;
    }
}

// ---------------------------------------------------------------------------
extern "C" void kernel_launch(void* const* d_in, const int* in_sizes, int n_in,
                              void* d_out, int out_size) {
    const float* x     = (const float*)d_in[0];
    const float* wa    = (const float*)d_in[1];
    const float* e     = (const float*)d_in[2];
    const float* W_w   = (const float*)d_in[3];
    const float* W_b   = (const float*)d_in[4];
    const float* Wx_w  = (const float*)d_in[5];
    const float* Wx_b  = (const float*)d_in[6];
    const float* Wxx_w = (const float*)d_in[7];
    const float* Wxx_b = (const float*)d_in[8];

    float* out     = (float*)d_out;            // (B,L,D)
    float* adj_out = out + 8 * 256 * 128;      // (B,H,L,L)

    k_gcn<<<256, 512>>>(x, wa, W_w, W_b, Wx_w, Wxx_w, Wxx_b, out);

    cudaLaunchConfig_t cfg = {};
    cfg.gridDim  = dim3(2048);
    cfg.blockDim = dim3(256);
    cudaLaunchAttribute attr[1];
    attr[0].id = cudaLaunchAttributeProgrammaticStreamSerialization;
    attr[0].val.programmaticStreamSerializationAllowed = 1;
    cfg.attrs    = attr;
    cfg.numAttrs = 1;
    cudaLaunchKernelEx(&cfg, k_adj, wa, e, Wx_w, Wx_b, adj_out);
}